// round 5
// baseline (speedup 1.0000x reference)
#include <cuda_runtime.h>
#include <cstdint>

#define S_LEN 2048
#define DIMM  2048
#define NH    16
#define NKV   8
#define HD    128
#define NTOK  4096
#define QKV_OUT 4096
#define BQ    64
#define BKT   64

typedef unsigned long long u64;
typedef unsigned int u32;

// ---------------- helpers ----------------
__device__ __forceinline__ u32 f2tf(float x) {
    u32 r; asm("cvt.rna.tf32.f32 %0, %1;" : "=r"(r) : "f"(x)); return r;
}
__device__ __forceinline__ void mma8(float* d, const u32* a, const u32* b) {
    asm volatile("mma.sync.aligned.m16n8k8.row.col.f32.tf32.tf32.f32 "
        "{%0,%1,%2,%3}, {%4,%5,%6,%7}, {%8,%9}, {%0,%1,%2,%3};"
        : "+f"(d[0]), "+f"(d[1]), "+f"(d[2]), "+f"(d[3])
        : "r"(a[0]), "r"(a[1]), "r"(a[2]), "r"(a[3]), "r"(b[0]), "r"(b[1]));
}
__device__ __forceinline__ float sel4(float a, float b, float c, float d, int s) {
    float lo = (s & 1) ? b : a;
    float hi = (s & 1) ? d : c;
    return (s & 2) ? hi : lo;
}
// packed f32x2 helpers (flash kernel)
__device__ __forceinline__ void fma2(u64 &d, u64 a, u64 b) {
    asm("fma.rn.f32x2 %0, %1, %2, %0;" : "+l"(d) : "l"(a), "l"(b));
}
__device__ __forceinline__ u64 mul2(u64 a, u64 b) {
    u64 d; asm("mul.rn.f32x2 %0, %1, %2;" : "=l"(d) : "l"(a), "l"(b)); return d;
}
__device__ __forceinline__ u64 pack2(float x) {
    u64 r; asm("mov.b64 %0, {%1, %1};" : "=l"(r) : "f"(x)); return r;
}

// ---------------- scratch ----------------
__device__ float g_qkv[(size_t)NTOK * QKV_OUT];
__device__ float g_q[(size_t)NTOK * NH * HD];
__device__ float g_k[(size_t)NTOK * NKV * HD];
__device__ float g_attn[(size_t)NTOK * DIMM];

// ---------------- tf32 mma.sync GEMM: C[M,N] = A[M,K] * B[N,K]^T ----------------
// CTA 128x128, 8 warps of 64x32, K staged 16, double-buffered smem (frag-major).
__global__ __launch_bounds__(256, 2) void gemm_mma(
    const float* __restrict__ A, const float* __restrict__ B,
    float* __restrict__ C, int M, int N, int K)
{
    __shared__ u32 sm[8192];  // 2 bufs x (A 2048 + B 2048) u32
    const int tid = threadIdx.x, w = tid >> 5, L = tid & 31;
    const int m0 = blockIdx.y * 128, n0 = blockIdx.x * 128;

    // writer A lane decode: bank bijection (g&1, cl, ch, half)
    const int a_gb = (L >> 4) & 1, a_ch = (L >> 3) & 1, a_half = (L >> 2) & 1, a_gp = L & 3;
    const int a_g  = a_gp * 2 + a_gb;
    const int a_r  = w * 16 + a_half * 8 + a_g;
    const int a_reg = a_half + 2 * a_ch;
    // writer B lane decode
    const int b_n8 = ((L & 1) << 2) | ((L >> 3) & 3);
    const int b_ch = (L >> 2) & 1;
    const int b_nt = w * 2 + ((L >> 1) & 1);
    const int b_r  = b_nt * 8 + b_n8;

    const float* Ag = A + (size_t)(m0 + a_r) * K + a_ch * 4;
    const float* Bg = B + (size_t)(n0 + b_r) * K + b_ch * 4;

    const int mw = w & 1, nq = w >> 1;

    float acc[4][4][4];
    #pragma unroll
    for (int i = 0; i < 4; i++)
        #pragma unroll
        for (int j = 0; j < 4; j++)
            #pragma unroll
            for (int q = 0; q < 4; q++) acc[i][j][q] = 0.f;

    const int S = K >> 4;
    float4 pa[2], pb[2];
    pa[0] = *(const float4*)(Ag);     pa[1] = *(const float4*)(Ag + 8);
    pb[0] = *(const float4*)(Bg);     pb[1] = *(const float4*)(Bg + 8);

    for (int s = 0; s < S; s++) {
        u32* smc = sm + (s & 1) * 4096;
        // ---- STS stage s (frag-major, rotated for conflict-free banks) ----
        #pragma unroll
        for (int i = 0; i < 2; i++) {
            const u32 abase = (u32)((w * 2 + i) * 128 + a_g * 16 + a_reg);
            const u32 bbase = (u32)(2048 + (b_nt * 2 + i) * 64 + b_n8 * 8 + b_ch);
            float4 va = pa[i], vb = pb[i];
            #pragma unroll
            for (int j = 0; j < 4; j++) {
                int cl = (j + L) & 3;
                smc[abase + cl * 4] = f2tf(sel4(va.x, va.y, va.z, va.w, cl));
            }
            #pragma unroll
            for (int j = 0; j < 4; j++) {
                int cl = (j + L) & 3;
                smc[bbase + cl * 2] = f2tf(sel4(vb.x, vb.y, vb.z, vb.w, cl));
            }
        }
        __syncthreads();
        // ---- prefetch stage s+1 ----
        if (s + 1 < S) {
            const float* Ag2 = Ag + (s + 1) * 16;
            const float* Bg2 = Bg + (s + 1) * 16;
            pa[0] = *(const float4*)(Ag2);     pa[1] = *(const float4*)(Ag2 + 8);
            pb[0] = *(const float4*)(Bg2);     pb[1] = *(const float4*)(Bg2 + 8);
        }
        // ---- compute 2 k8 steps ----
        #pragma unroll
        for (int kk = 0; kk < 2; kk++) {
            u32 af[4][4]; u32 bf[4][2];
            #pragma unroll
            for (int mt = 0; mt < 4; mt++) {
                uint4 t = *(const uint4*)&smc[(((mw * 4 + mt) * 2 + kk) * 128) + L * 4];
                af[mt][0] = t.x; af[mt][1] = t.y; af[mt][2] = t.z; af[mt][3] = t.w;
            }
            #pragma unroll
            for (int nt = 0; nt < 4; nt++) {
                uint2 t = *(const uint2*)&smc[2048 + ((nq * 4 + nt) * 2 + kk) * 64 + L * 2];
                bf[nt][0] = t.x; bf[nt][1] = t.y;
            }
            #pragma unroll
            for (int mt = 0; mt < 4; mt++)
                #pragma unroll
                for (int nt = 0; nt < 4; nt++)
                    mma8(acc[mt][nt], af[mt], bf[nt]);
        }
        __syncthreads();
    }

    // ---- epilogue ----
    #pragma unroll
    for (int mt = 0; mt < 4; mt++) {
        const int r0 = m0 + mw * 64 + mt * 16 + (L >> 2);
        #pragma unroll
        for (int nt = 0; nt < 4; nt++) {
            const int c0 = n0 + nq * 32 + nt * 8 + (L & 3) * 2;
            float* p0 = C + (size_t)r0 * N + c0;
            float* p1 = C + (size_t)(r0 + 8) * N + c0;
            *(float2*)p0 = make_float2(acc[mt][nt][0], acc[mt][nt][1]);
            *(float2*)p1 = make_float2(acc[mt][nt][2], acc[mt][nt][3]);
        }
    }
}

// ---------------- fused per-head RMSNorm + RoPE ----------------
__global__ __launch_bounds__(128) void norm_rope_kernel(
    const float* __restrict__ freqs,
    const float* __restrict__ qw, const float* __restrict__ kw)
{
    const int t  = blockIdx.x;
    const int hh = blockIdx.y;
    const int d  = threadIdx.x;
    const bool isq = hh < NH;
    const int h = isq ? hh : hh - NH;
    const size_t base = (size_t)t * QKV_OUT + (isq ? h*HD : NH*HD + h*HD);
    float v = g_qkv[base + d];

    float ss = v * v;
    #pragma unroll
    for (int o = 16; o; o >>= 1) ss += __shfl_xor_sync(0xffffffffu, ss, o);
    __shared__ float red[4];
    if ((d & 31) == 0) red[d >> 5] = ss;
    __syncthreads();
    ss = red[0] + red[1] + red[2] + red[3];

    float w  = isq ? qw[d] : kw[d];
    float xn = v * rsqrtf(ss * (1.0f / HD) + 1e-5f) * w;

    float other = __shfl_xor_sync(0xffffffffu, xn, 1);
    int f = d >> 1, r = d & 1;
    float x0 = (r == 0) ? xn : other;
    float x1 = (r == 0) ? other : xn;
    int s = t & (S_LEN - 1);
    const float* fc = freqs + ((size_t)s * 64 + f) * 4 + r * 2;
    float outv = fc[0] * x0 + fc[1] * x1;

    if (isq) g_q[((size_t)t * NH  + h) * HD + d] = outv;
    else     g_k[((size_t)t * NKV + h) * HD + d] = outv;
}

// ---------------- fp32 flash attention (register softmax, FFMA2) ----------------
#define FL_SMEM_FLOATS (2*128*68 + 64*132 + 64*65 + 16)
#define FL_SMEM_BYTES  (FL_SMEM_FLOATS * 4)

__global__ __launch_bounds__(256) void flash_kernel(const float* __restrict__ mask)
{
    extern __shared__ float sm[];
    float* Qs  = sm;
    float* Ks  = sm + 128*68;
    float* Vs  = sm + 2*128*68;
    float* Ps  = Vs + 64*132;

    const int tid  = threadIdx.x;
    const int lane = tid & 31, w = tid >> 5;
    const int tx = tid & 15, ty = tid >> 4;
    const int h = blockIdx.y, b = blockIdx.z;
    const int hkv = h >> 1;
    const int q0 = blockIdx.x * BQ;
    const int tok0 = b * S_LEN;
    const float scale = 0.088388347762f;

    {
        int n  = lane + ((w & 1) << 5);
        int qb = (w >> 1) * 8;
        const float* qr = g_q + ((size_t)(tok0 + q0 + n) * NH + h) * HD;
        #pragma unroll
        for (int i = 0; i < 8; i++) {
            int d0 = (qb + i) * 4;
            float4 v = *(const float4*)(qr + d0);
            Qs[(d0+0)*68 + n] = v.x;
            Qs[(d0+1)*68 + n] = v.y;
            Qs[(d0+2)*68 + n] = v.z;
            Qs[(d0+3)*68 + n] = v.w;
        }
    }

    float m_r[4], l_r[4];
    #pragma unroll
    for (int i = 0; i < 4; i++) { m_r[i] = -1e30f; l_r[i] = 0.f; }
    u64 acc[4][4] = {};

    for (int kt = 0; kt < S_LEN; kt += BKT) {
        __syncthreads();
        {
            int n  = lane + ((w & 1) << 5);
            int qb = (w >> 1) * 8;
            const float* kr = g_k + ((size_t)(tok0 + kt + n) * NKV + hkv) * HD;
            #pragma unroll
            for (int i = 0; i < 8; i++) {
                int d0 = (qb + i) * 4;
                float4 v = *(const float4*)(kr + d0);
                Ks[(d0+0)*68 + n] = v.x;
                Ks[(d0+1)*68 + n] = v.y;
                Ks[(d0+2)*68 + n] = v.z;
                Ks[(d0+3)*68 + n] = v.w;
            }
            #pragma unroll
            for (int i = 0; i < 8; i++) {
                int e = tid + i * 256;
                int row = e >> 5, quad = e & 31;
                float4 v = *(const float4*)(g_qkv + (size_t)(tok0 + kt + row) * QKV_OUT
                                            + (NH + NKV) * HD + hkv * HD + quad * 4);
                *(float4*)&Vs[row * 132 + quad * 4] = v;
            }
        }
        __syncthreads();

        u64 s2[4][2] = {};
        #pragma unroll 8
        for (int kk = 0; kk < HD; kk++) {
            float4 qa = *(const float4*)&Qs[kk*68 + ty*4];
            ulonglong2 kb = *(const ulonglong2*)&Ks[kk*68 + tx*4];
            float ra[4] = {qa.x,qa.y,qa.z,qa.w};
            #pragma unroll
            for (int i = 0; i < 4; i++) {
                u64 ai = pack2(ra[i]);
                fma2(s2[i][0], ai, kb.x);
                fma2(s2[i][1], ai, kb.y);
            }
        }

        float t[4][4];
        const float* mrow = mask + (size_t)b * S_LEN * S_LEN
                            + (size_t)(q0 + ty*4) * S_LEN + kt + tx*4;
        #pragma unroll
        for (int i = 0; i < 4; i++) {
            float lo0, hi0, lo1, hi1;
            asm("mov.b64 {%0, %1}, %2;" : "=f"(lo0), "=f"(hi0) : "l"(s2[i][0]));
            asm("mov.b64 {%0, %1}, %2;" : "=f"(lo1), "=f"(hi1) : "l"(s2[i][1]));
            float4 mv = *(const float4*)(mrow + (size_t)i * S_LEN);
            t[i][0] = lo0 * scale + mv.x;
            t[i][1] = hi0 * scale + mv.y;
            t[i][2] = lo1 * scale + mv.z;
            t[i][3] = hi1 * scale + mv.w;
        }

        float aa[4];
        #pragma unroll
        for (int i = 0; i < 4; i++) {
            float mx = fmaxf(fmaxf(t[i][0], t[i][1]), fmaxf(t[i][2], t[i][3]));
            #pragma unroll
            for (int o = 1; o < 16; o <<= 1)
                mx = fmaxf(mx, __shfl_xor_sync(0xffffffffu, mx, o));
            float mn = fmaxf(m_r[i], mx);
            aa[i] = __expf(m_r[i] - mn);
            m_r[i] = mn;
            float sum = 0.f;
            #pragma unroll
            for (int j = 0; j < 4; j++) {
                t[i][j] = __expf(t[i][j] - mn);
                sum += t[i][j];
            }
            #pragma unroll
            for (int o = 1; o < 16; o <<= 1)
                sum += __shfl_xor_sync(0xffffffffu, sum, o);
            l_r[i] = l_r[i] * aa[i] + sum;
        }

        #pragma unroll
        for (int j = 0; j < 4; j++)
            #pragma unroll
            for (int i = 0; i < 4; i++)
                Ps[(tx*4+j)*65 + ty*4 + i] = t[i][j];
        __syncthreads();

        #pragma unroll
        for (int i = 0; i < 4; i++) {
            u64 av = pack2(aa[i]);
            #pragma unroll
            for (int j = 0; j < 4; j++) acc[i][j] = mul2(acc[i][j], av);
        }
        #pragma unroll 4
        for (int jj = 0; jj < BKT; jj++) {
            ulonglong2 v0 = *(const ulonglong2*)&Vs[jj*132 + tx*8];
            ulonglong2 v1 = *(const ulonglong2*)&Vs[jj*132 + tx*8 + 4];
            u64 rv[4] = {v0.x, v0.y, v1.x, v1.y};
            #pragma unroll
            for (int i = 0; i < 4; i++) {
                u64 pi = pack2(Ps[jj*65 + ty*4 + i]);
                #pragma unroll
                for (int j = 0; j < 4; j++) fma2(acc[i][j], pi, rv[j]);
            }
        }
    }

    #pragma unroll
    for (int i = 0; i < 4; i++) {
        u64 lv = pack2(1.0f / l_r[i]);
        float* op = g_attn + (size_t)(tok0 + q0 + ty*4 + i) * DIMM + h*HD + tx*8;
        ((ulonglong2*)op)[0] = make_ulonglong2(mul2(acc[i][0], lv), mul2(acc[i][1], lv));
        ((ulonglong2*)op)[1] = make_ulonglong2(mul2(acc[i][2], lv), mul2(acc[i][3], lv));
    }
}

// ---------------- launch ----------------
extern "C" void kernel_launch(void* const* d_in, const int* in_sizes, int n_in,
                              void* d_out, int out_size)
{
    const float* x     = (const float*)d_in[0];
    const float* mask  = (const float*)d_in[1];
    const float* freqs = (const float*)d_in[2];
    const float* w_qkv = (const float*)d_in[3];
    const float* w_out = (const float*)d_in[4];
    const float* q_w   = (const float*)d_in[5];
    const float* k_w   = (const float*)d_in[6];
    float* out = (float*)d_out;

    float *qkv_p, *attn_p;
    cudaGetSymbolAddress((void**)&qkv_p,  g_qkv);
    cudaGetSymbolAddress((void**)&attn_p, g_attn);

    cudaFuncSetAttribute(flash_kernel, cudaFuncAttributeMaxDynamicSharedMemorySize, FL_SMEM_BYTES);

    // QKV projection (tf32 tensor cores): [4096,4096] = x[4096,2048] * w_qkv^T
    gemm_mma<<<dim3(QKV_OUT/128, NTOK/128), 256>>>(x, w_qkv, qkv_p, NTOK, QKV_OUT, DIMM);
    norm_rope_kernel<<<dim3(NTOK, NH + NKV), 128>>>(freqs, q_w, k_w);
    flash_kernel<<<dim3(S_LEN/BQ, NH, 2), 256, FL_SMEM_BYTES>>>(mask);
    // out projection: [4096,2048] = attn[4096,2048] * w_out^T
    gemm_mma<<<dim3(DIMM/128, NTOK/128), 256>>>(attn_p, w_out, out, NTOK, DIMM, DIMM);
}

// round 6
// speedup vs baseline: 2.7345x; 2.7345x over previous
#include <cuda_runtime.h>
#include <cuda_bf16.h>
#include <cstdint>

#define S_LEN 2048
#define DIMM  2048
#define NH    16
#define NKV   8
#define HD    128
#define NTOK  4096
#define QKV_OUT 4096

typedef unsigned int u32;
typedef unsigned long long u64;
typedef __nv_bfloat16 bf16;

// ---------------- PTX helpers ----------------
__device__ __forceinline__ u32 smem_u32(const void* p) {
    u32 a; asm("{ .reg .u64 t; cvta.to.shared.u64 t, %1; cvt.u32.u64 %0, t; }" : "=r"(a) : "l"(p));
    return a;
}
#define CP16(dst, src) asm volatile("cp.async.cg.shared.global [%0], [%1], 16;" :: "r"(dst), "l"(src))
#define CPC()  asm volatile("cp.async.commit_group;" ::: "memory")
#define CPW0() asm volatile("cp.async.wait_group 0;" ::: "memory")
#define CPW1() asm volatile("cp.async.wait_group 1;" ::: "memory")

__device__ __forceinline__ void ldsm4(u32 &r0, u32 &r1, u32 &r2, u32 &r3, u32 a) {
    asm volatile("ldmatrix.sync.aligned.m8n8.x4.shared.b16 {%0,%1,%2,%3}, [%4];"
        : "=r"(r0), "=r"(r1), "=r"(r2), "=r"(r3) : "r"(a));
}
__device__ __forceinline__ void ldsm4t(u32 &r0, u32 &r1, u32 &r2, u32 &r3, u32 a) {
    asm volatile("ldmatrix.sync.aligned.m8n8.x4.trans.shared.b16 {%0,%1,%2,%3}, [%4];"
        : "=r"(r0), "=r"(r1), "=r"(r2), "=r"(r3) : "r"(a));
}
__device__ __forceinline__ void mmabf(float* d, const u32* a, const u32* b) {
    asm volatile("mma.sync.aligned.m16n8k16.row.col.f32.bf16.bf16.f32 "
        "{%0,%1,%2,%3},{%4,%5,%6,%7},{%8,%9},{%0,%1,%2,%3};"
        : "+f"(d[0]), "+f"(d[1]), "+f"(d[2]), "+f"(d[3])
        : "r"(a[0]), "r"(a[1]), "r"(a[2]), "r"(a[3]), "r"(b[0]), "r"(b[1]));
}
// pack f0(lo half),f1(hi half) to bf16x2 hi; residual pack in lo
__device__ __forceinline__ u32 split2(float f0, float f1, u32 &lo) {
    u32 h; asm("cvt.rn.bf16x2.f32 %0, %1, %2;" : "=r"(h) : "f"(f1), "f"(f0));
    float h0 = __uint_as_float(h << 16);
    float h1 = __uint_as_float(h & 0xffff0000u);
    asm("cvt.rn.bf16x2.f32 %0, %1, %2;" : "=r"(lo) : "f"(f1 - h1), "f"(f0 - h0));
    return h;
}

// ---------------- scratch ----------------
__device__ float g_qkv[(size_t)NTOK * QKV_OUT];            // fp32 QKV output
__device__ bf16 g_xh[(size_t)NTOK * DIMM],    g_xl[(size_t)NTOK * DIMM];
__device__ bf16 g_wqh[(size_t)QKV_OUT * DIMM], g_wql[(size_t)QKV_OUT * DIMM];
__device__ bf16 g_woh[(size_t)DIMM * DIMM],   g_wol[(size_t)DIMM * DIMM];
__device__ bf16 g_qh[(size_t)NTOK * NH * HD], g_ql[(size_t)NTOK * NH * HD];
__device__ bf16 g_kh[(size_t)NTOK * NKV * HD], g_kl[(size_t)NTOK * NKV * HD];
__device__ bf16 g_vh[(size_t)NTOK * NKV * HD], g_vl[(size_t)NTOK * NKV * HD];
__device__ bf16 g_ah[(size_t)NTOK * DIMM],    g_al[(size_t)NTOK * DIMM];

// ---------------- elementwise split fp32 -> bf16 hi/lo ----------------
__global__ __launch_bounds__(256) void split_bf(
    const float4* __restrict__ in, uint2* __restrict__ hi, uint2* __restrict__ lo, int n4)
{
    int i = blockIdx.x * 256 + threadIdx.x;
    if (i >= n4) return;
    float4 v = in[i];
    u32 l0, l1;
    u32 h0 = split2(v.x, v.y, l0);
    u32 h1 = split2(v.z, v.w, l1);
    hi[i] = make_uint2(h0, h1);
    lo[i] = make_uint2(l0, l1);
}

// V section of qkv -> planes [t][kv*128]
__global__ __launch_bounds__(256) void split_v_kernel()
{
    int i = blockIdx.x * 256 + threadIdx.x;
    if (i >= NTOK * 256) return;
    int t = i >> 8, j = (i & 255) * 4;
    float4 v = *(const float4*)(g_qkv + (size_t)t * QKV_OUT + 3072 + j);
    u32 l0, l1;
    u32 h0 = split2(v.x, v.y, l0);
    u32 h1 = split2(v.z, v.w, l1);
    *(uint2*)&g_vh[(size_t)t * 1024 + j] = make_uint2(h0, h1);
    *(uint2*)&g_vl[(size_t)t * 1024 + j] = make_uint2(l0, l1);
}

// ---------------- bf16x3 GEMM: C[M,N] = A[M,K] * B[N,K]^T ----------------
// CTA 128x128, 8 warps (64x32 each), k32 stages, cp.async double buffer.
// smem rows: 128B = [hi 4 chunks][lo 4 chunks], chunk swizzle c^(r&7).
#define GEMM_SMEM (2 * 32768)
__global__ __launch_bounds__(256, 2) void gemm_bf3(
    const bf16* __restrict__ Ah, const bf16* __restrict__ Al,
    const bf16* __restrict__ Bh, const bf16* __restrict__ Bl,
    float* __restrict__ C, int M, int N, int K)
{
    extern __shared__ char gsm[];
    const u32 sb = smem_u32(gsm);
    const int tid = threadIdx.x, L = tid & 31, w = tid >> 5;
    const int m0 = blockIdx.y * 128, n0 = blockIdx.x * 128;
    const int mw = w & 1, nq = w >> 1;

    float acc[4][4][4];
    #pragma unroll
    for (int a = 0; a < 4; a++)
        #pragma unroll
        for (int b = 0; b < 4; b++)
            #pragma unroll
            for (int c = 0; c < 4; c++) acc[a][b][c] = 0.f;

    const int NS = K >> 5;
    // per-thread cp ids: 4 chunks A + 4 chunks B
    const int id0 = tid;

    #define GEMM_STAGE_CP(s) do { \
        int k0 = (s) * 32; \
        u32 bufb = sb + ((s) & 1) * 32768; \
        _Pragma("unroll") \
        for (int rr = 0; rr < 4; rr++) { \
            int id = id0 + rr * 256; \
            int row = id >> 3, c = id & 7, pl = c >> 2, kc = c & 3; \
            const bf16* srcA = (pl ? Al : Ah) + (size_t)(m0 + row) * K + k0 + kc * 8; \
            CP16(bufb + row * 128 + (((u32)(c ^ (row & 7))) << 4), srcA); \
            const bf16* srcB = (pl ? Bl : Bh) + (size_t)(n0 + row) * K + k0 + kc * 8; \
            CP16(bufb + 16384 + row * 128 + (((u32)(c ^ (row & 7))) << 4), srcB); \
        } \
    } while (0)

    GEMM_STAGE_CP(0); CPC();

    for (int s = 0; s < NS; s++) {
        if (s + 1 < NS) { GEMM_STAGE_CP(s + 1); CPC(); CPW1(); }
        else CPW0();
        __syncthreads();
        u32 ab = sb + (s & 1) * 32768;
        u32 bb = ab + 16384;
        #pragma unroll
        for (int ks = 0; ks < 2; ks++) {
            u32 ah[4][4], al[4][4], bh[4][2], bl[4][2];
            #pragma unroll
            for (int mt = 0; mt < 4; mt++) {
                int row = mw * 64 + mt * 16 + (L & 7) + ((L >> 3) & 1) * 8;
                int ch = ks * 2 + (L >> 4);
                u32 base = ab + row * 128;
                ldsm4(ah[mt][0], ah[mt][1], ah[mt][2], ah[mt][3],
                      base + ((u32)(ch ^ (row & 7)) << 4));
                ldsm4(al[mt][0], al[mt][1], al[mt][2], al[mt][3],
                      base + ((u32)((ch + 4) ^ (row & 7)) << 4));
            }
            #pragma unroll
            for (int p = 0; p < 2; p++) {
                int row = nq * 32 + p * 16 + (L & 7) + (L >> 4) * 8;
                int ch = ks * 2 + ((L >> 3) & 1);
                u32 base = bb + row * 128;
                u32 r0, r1, r2, r3;
                ldsm4(r0, r1, r2, r3, base + ((u32)(ch ^ (row & 7)) << 4));
                bh[2*p][0] = r0; bh[2*p][1] = r1; bh[2*p+1][0] = r2; bh[2*p+1][1] = r3;
                ldsm4(r0, r1, r2, r3, base + ((u32)((ch + 4) ^ (row & 7)) << 4));
                bl[2*p][0] = r0; bl[2*p][1] = r1; bl[2*p+1][0] = r2; bl[2*p+1][1] = r3;
            }
            #pragma unroll
            for (int mt = 0; mt < 4; mt++)
                #pragma unroll
                for (int nt = 0; nt < 4; nt++) {
                    mmabf(acc[mt][nt], ah[mt], bh[nt]);
                    mmabf(acc[mt][nt], ah[mt], bl[nt]);
                    mmabf(acc[mt][nt], al[mt], bh[nt]);
                }
        }
        __syncthreads();
    }

    #pragma unroll
    for (int mt = 0; mt < 4; mt++) {
        int r0 = m0 + mw * 64 + mt * 16 + (L >> 2);
        #pragma unroll
        for (int nt = 0; nt < 4; nt++) {
            int c0 = n0 + nq * 32 + nt * 8 + (L & 3) * 2;
            *(float2*)(C + (size_t)r0 * N + c0)       = make_float2(acc[mt][nt][0], acc[mt][nt][1]);
            *(float2*)(C + (size_t)(r0 + 8) * N + c0) = make_float2(acc[mt][nt][2], acc[mt][nt][3]);
        }
    }
}

// ---------------- fused RMSNorm + RoPE -> bf16 planes ----------------
__global__ __launch_bounds__(128) void norm_rope_kernel(
    const float* __restrict__ freqs,
    const float* __restrict__ qw, const float* __restrict__ kw)
{
    const int t  = blockIdx.x;
    const int hh = blockIdx.y;
    const int d  = threadIdx.x;
    const bool isq = hh < NH;
    const int h = isq ? hh : hh - NH;
    const size_t base = (size_t)t * QKV_OUT + (isq ? h*HD : NH*HD + h*HD);
    float v = g_qkv[base + d];

    float ss = v * v;
    #pragma unroll
    for (int o = 16; o; o >>= 1) ss += __shfl_xor_sync(0xffffffffu, ss, o);
    __shared__ float red[4];
    if ((d & 31) == 0) red[d >> 5] = ss;
    __syncthreads();
    ss = red[0] + red[1] + red[2] + red[3];

    float w  = isq ? qw[d] : kw[d];
    float xn = v * rsqrtf(ss * (1.0f / HD) + 1e-5f) * w;

    float other = __shfl_xor_sync(0xffffffffu, xn, 1);
    int f = d >> 1, r = d & 1;
    float x0 = (r == 0) ? xn : other;
    float x1 = (r == 0) ? other : xn;
    int s = t & (S_LEN - 1);
    const float* fc = freqs + ((size_t)s * 64 + f) * 4 + r * 2;
    float outv = fc[0] * x0 + fc[1] * x1;

    bf16 hb = __float2bfloat16(outv);
    bf16 lb = __float2bfloat16(outv - __bfloat162float(hb));
    if (isq) {
        size_t idx = ((size_t)t * NH + h) * HD + d;
        g_qh[idx] = hb; g_ql[idx] = lb;
    } else {
        size_t idx = ((size_t)t * NKV + h) * HD + d;
        g_kh[idx] = hb; g_kl[idx] = lb;
    }
}

// ---------------- tensor-core flash attention (bf16x3) ----------------
// grid (S/128, NH, B), 256 threads. smem: Q 64KB + 2 x (K 32KB + V 32KB) = 192KB.
// rows 512B = [hi 16 chunks][lo 16 chunks], swizzle c^(r&7).
#define FL_SMEM (65536 + 2 * 65536)
__global__ __launch_bounds__(256, 1) void flash_bf(const float* __restrict__ mask)
{
    extern __shared__ char fsm[];
    const u32 sb = smem_u32(fsm);
    const int tid = threadIdx.x, L = tid & 31, w = tid >> 5;
    const int h = blockIdx.y, b = blockIdx.z;
    const int hkv = h >> 1;
    const int q0 = blockIdx.x * 128;
    const int tok0 = b * S_LEN;
    const float scale = 0.088388347762f;

    // stage Q tile (group 0)
    #pragma unroll
    for (int i = 0; i < 16; i++) {
        int id = tid + i * 256;
        int row = id >> 5, c = id & 31, pl = c >> 4, cc = c & 15;
        const bf16* src = (pl ? g_ql : g_qh)
            + ((size_t)(tok0 + q0 + row) * NH + h) * HD + cc * 8;
        CP16(sb + row * 512 + ((u32)(c ^ (row & 7)) << 4), src);
    }
    CPC();

    #define FL_KV_CP(tt) do { \
        u32 bufb = sb + 65536 + ((tt) & 1) * 65536; \
        int kt_ = (tt) * 64; \
        _Pragma("unroll") \
        for (int i = 0; i < 16; i++) { \
            int id = tid + i * 256; \
            int tensor = id >> 11; \
            int rem = id & 2047; \
            int row = rem >> 5, c = rem & 31, pl = c >> 4, cc = c & 15; \
            const bf16* src; \
            if (tensor == 0) src = (pl ? g_kl : g_kh) \
                + ((size_t)(tok0 + kt_ + row) * NKV + hkv) * HD + cc * 8; \
            else             src = (pl ? g_vl : g_vh) \
                + ((size_t)(tok0 + kt_ + row) * NKV + hkv) * HD + cc * 8; \
            CP16(bufb + tensor * 32768 + row * 512 + ((u32)(c ^ (row & 7)) << 4), src); \
        } \
    } while (0)

    FL_KV_CP(0); CPC();

    float m0r = -1e30f, m1r = -1e30f, l0r = 0.f, l1r = 0.f;
    float acc[16][4];
    #pragma unroll
    for (int i = 0; i < 16; i++)
        #pragma unroll
        for (int j = 0; j < 4; j++) acc[i][j] = 0.f;

    const int g = L >> 2;
    const float* mp0 = mask + (size_t)b * S_LEN * S_LEN
                       + (size_t)(q0 + w * 16 + g) * S_LEN + (L & 3) * 2;

    for (int t = 0; t < 32; t++) {
        if (t + 1 < 32) { FL_KV_CP(t + 1); CPC(); CPW1(); }
        else CPW0();
        __syncthreads();
        u32 kb = sb + 65536 + (t & 1) * 65536;
        u32 vb = kb + 32768;
        const int kt = t * 64;

        // ---- S = Q K^T (3 planes) ----
        float s[8][4];
        #pragma unroll
        for (int f = 0; f < 8; f++)
            #pragma unroll
            for (int j = 0; j < 4; j++) s[f][j] = 0.f;

        #pragma unroll
        for (int kd = 0; kd < 8; kd++) {
            u32 qh[4], ql[4];
            {
                int row = w * 16 + (L & 7) + ((L >> 3) & 1) * 8;
                int ch = kd * 2 + (L >> 4);
                u32 base = sb + row * 512;
                ldsm4(qh[0], qh[1], qh[2], qh[3], base + ((u32)(ch ^ (row & 7)) << 4));
                ldsm4(ql[0], ql[1], ql[2], ql[3], base + ((u32)((ch + 16) ^ (row & 7)) << 4));
            }
            u32 kh[8][2], kl[8][2];
            #pragma unroll
            for (int p = 0; p < 4; p++) {
                int row = p * 16 + (L & 7) + (L >> 4) * 8;
                int ch = kd * 2 + ((L >> 3) & 1);
                u32 base = kb + row * 512;
                u32 r0, r1, r2, r3;
                ldsm4(r0, r1, r2, r3, base + ((u32)(ch ^ (row & 7)) << 4));
                kh[2*p][0] = r0; kh[2*p][1] = r1; kh[2*p+1][0] = r2; kh[2*p+1][1] = r3;
                ldsm4(r0, r1, r2, r3, base + ((u32)((ch + 16) ^ (row & 7)) << 4));
                kl[2*p][0] = r0; kl[2*p][1] = r1; kl[2*p+1][0] = r2; kl[2*p+1][1] = r3;
            }
            #pragma unroll
            for (int f = 0; f < 8; f++) {
                mmabf(s[f], qh, kh[f]);
                mmabf(s[f], qh, kl[f]);
                mmabf(s[f], ql, kh[f]);
            }
        }

        // ---- scale + mask + online softmax ----
        float mx0 = -1e30f, mx1 = -1e30f;
        #pragma unroll
        for (int f = 0; f < 8; f++) {
            float2 mv0 = *(const float2*)(mp0 + kt + f * 8);
            float2 mv1 = *(const float2*)(mp0 + 8 * S_LEN + kt + f * 8);
            s[f][0] = s[f][0] * scale + mv0.x;
            s[f][1] = s[f][1] * scale + mv0.y;
            s[f][2] = s[f][2] * scale + mv1.x;
            s[f][3] = s[f][3] * scale + mv1.y;
            mx0 = fmaxf(mx0, fmaxf(s[f][0], s[f][1]));
            mx1 = fmaxf(mx1, fmaxf(s[f][2], s[f][3]));
        }
        mx0 = fmaxf(mx0, __shfl_xor_sync(0xffffffffu, mx0, 1));
        mx0 = fmaxf(mx0, __shfl_xor_sync(0xffffffffu, mx0, 2));
        mx1 = fmaxf(mx1, __shfl_xor_sync(0xffffffffu, mx1, 1));
        mx1 = fmaxf(mx1, __shfl_xor_sync(0xffffffffu, mx1, 2));
        float mn0 = fmaxf(m0r, mx0), mn1 = fmaxf(m1r, mx1);
        float a0 = __expf(m0r - mn0), a1 = __expf(m1r - mn1);
        m0r = mn0; m1r = mn1;
        float sum0 = 0.f, sum1 = 0.f;
        #pragma unroll
        for (int f = 0; f < 8; f++) {
            s[f][0] = __expf(s[f][0] - mn0); sum0 += s[f][0];
            s[f][1] = __expf(s[f][1] - mn0); sum0 += s[f][1];
            s[f][2] = __expf(s[f][2] - mn1); sum1 += s[f][2];
            s[f][3] = __expf(s[f][3] - mn1); sum1 += s[f][3];
        }
        sum0 += __shfl_xor_sync(0xffffffffu, sum0, 1);
        sum0 += __shfl_xor_sync(0xffffffffu, sum0, 2);
        sum1 += __shfl_xor_sync(0xffffffffu, sum1, 1);
        sum1 += __shfl_xor_sync(0xffffffffu, sum1, 2);
        l0r = l0r * a0 + sum0;
        l1r = l1r * a1 + sum1;

        // ---- P -> bf16 hi/lo A-frags ----
        u32 ph[4][4], pl[4][4];
        #pragma unroll
        for (int kg = 0; kg < 4; kg++) {
            ph[kg][0] = split2(s[2*kg][0],   s[2*kg][1],   pl[kg][0]);
            ph[kg][1] = split2(s[2*kg][2],   s[2*kg][3],   pl[kg][1]);
            ph[kg][2] = split2(s[2*kg+1][0], s[2*kg+1][1], pl[kg][2]);
            ph[kg][3] = split2(s[2*kg+1][2], s[2*kg+1][3], pl[kg][3]);
        }

        // ---- rescale acc ----
        #pragma unroll
        for (int df = 0; df < 16; df++) {
            acc[df][0] *= a0; acc[df][1] *= a0;
            acc[df][2] *= a1; acc[df][3] *= a1;
        }

        // ---- O += P V (3 planes) ----
        #pragma unroll
        for (int kg = 0; kg < 4; kg++) {
            #pragma unroll
            for (int dp = 0; dp < 8; dp++) {
                int row = kg * 16 + (L & 7) + ((L >> 3) & 1) * 8;
                int ch = dp * 2 + (L >> 4);
                u32 base = vb + row * 512;
                u32 vh0[2], vh1[2], vl0[2], vl1[2];
                {
                    u32 r0, r1, r2, r3;
                    ldsm4t(r0, r1, r2, r3, base + ((u32)(ch ^ (row & 7)) << 4));
                    vh0[0] = r0; vh0[1] = r1; vh1[0] = r2; vh1[1] = r3;
                    ldsm4t(r0, r1, r2, r3, base + ((u32)((ch + 16) ^ (row & 7)) << 4));
                    vl0[0] = r0; vl0[1] = r1; vl1[0] = r2; vl1[1] = r3;
                }
                mmabf(acc[2*dp],   ph[kg], vh0);
                mmabf(acc[2*dp],   ph[kg], vl0);
                mmabf(acc[2*dp],   pl[kg], vh0);
                mmabf(acc[2*dp+1], ph[kg], vh1);
                mmabf(acc[2*dp+1], ph[kg], vl1);
                mmabf(acc[2*dp+1], pl[kg], vh1);
            }
        }
        __syncthreads();
    }

    // ---- epilogue: normalize + split to attn planes ----
    float inv0 = 1.0f / l0r, inv1 = 1.0f / l1r;
    int qrow = tok0 + q0 + w * 16 + g;
    #pragma unroll
    for (int df = 0; df < 16; df++) {
        int col = h * HD + df * 8 + (L & 3) * 2;
        u32 lo_;
        u32 hi_ = split2(acc[df][0] * inv0, acc[df][1] * inv0, lo_);
        *(u32*)&g_ah[(size_t)qrow * DIMM + col] = hi_;
        *(u32*)&g_al[(size_t)qrow * DIMM + col] = lo_;
        hi_ = split2(acc[df][2] * inv1, acc[df][3] * inv1, lo_);
        *(u32*)&g_ah[(size_t)(qrow + 8) * DIMM + col] = hi_;
        *(u32*)&g_al[(size_t)(qrow + 8) * DIMM + col] = lo_;
    }
}

// ---------------- launch ----------------
extern "C" void kernel_launch(void* const* d_in, const int* in_sizes, int n_in,
                              void* d_out, int out_size)
{
    const float* x     = (const float*)d_in[0];
    const float* mask  = (const float*)d_in[1];
    const float* freqs = (const float*)d_in[2];
    const float* w_qkv = (const float*)d_in[3];
    const float* w_out = (const float*)d_in[4];
    const float* q_w   = (const float*)d_in[5];
    const float* k_w   = (const float*)d_in[6];
    float* out = (float*)d_out;

    float* qkv_p;
    bf16 *xh, *xl, *wqh, *wql, *woh, *wol, *ah, *al;
    cudaGetSymbolAddress((void**)&qkv_p, g_qkv);
    cudaGetSymbolAddress((void**)&xh,  g_xh);  cudaGetSymbolAddress((void**)&xl,  g_xl);
    cudaGetSymbolAddress((void**)&wqh, g_wqh); cudaGetSymbolAddress((void**)&wql, g_wql);
    cudaGetSymbolAddress((void**)&woh, g_woh); cudaGetSymbolAddress((void**)&wol, g_wol);
    cudaGetSymbolAddress((void**)&ah,  g_ah);  cudaGetSymbolAddress((void**)&al,  g_al);

    cudaFuncSetAttribute(gemm_bf3, cudaFuncAttributeMaxDynamicSharedMemorySize, GEMM_SMEM);
    cudaFuncSetAttribute(flash_bf, cudaFuncAttributeMaxDynamicSharedMemorySize, FL_SMEM);

    const int N4_X  = NTOK * DIMM / 4;
    const int N4_WQ = QKV_OUT * DIMM / 4;
    const int N4_WO = DIMM * DIMM / 4;

    split_bf<<<(N4_X  + 255)/256, 256>>>((const float4*)x,     (uint2*)xh,  (uint2*)xl,  N4_X);
    split_bf<<<(N4_WQ + 255)/256, 256>>>((const float4*)w_qkv, (uint2*)wqh, (uint2*)wql, N4_WQ);
    split_bf<<<(N4_WO + 255)/256, 256>>>((const float4*)w_out, (uint2*)woh, (uint2*)wol, N4_WO);

    // QKV projection
    gemm_bf3<<<dim3(QKV_OUT/128, NTOK/128), 256, GEMM_SMEM>>>(
        xh, xl, wqh, wql, qkv_p, NTOK, QKV_OUT, DIMM);

    norm_rope_kernel<<<dim3(NTOK, NH + NKV), 128>>>(freqs, q_w, k_w);
    split_v_kernel<<<(NTOK * 256 + 255)/256, 256>>>();

    flash_bf<<<dim3(S_LEN/128, NH, 2), 256, FL_SMEM>>>(mask);

    // out projection
    gemm_bf3<<<dim3(DIMM/128, NTOK/128), 256, GEMM_SMEM>>>(
        ah, al, woh, wol, out, NTOK, DIMM, DIMM);
}

// round 7
// speedup vs baseline: 2.7531x; 1.0068x over previous
#include <cuda_runtime.h>
#include <cuda_bf16.h>
#include <cstdint>

#define S_LEN 2048
#define DIMM  2048
#define NH    16
#define NKV   8
#define HD    128
#define NTOK  4096
#define QKV_OUT 4096

typedef unsigned int u32;
typedef unsigned long long u64;
typedef __nv_bfloat16 bf16;

// ---------------- PTX helpers ----------------
__device__ __forceinline__ u32 smem_u32(const void* p) {
    u32 a; asm("{ .reg .u64 t; cvta.to.shared.u64 t, %1; cvt.u32.u64 %0, t; }" : "=r"(a) : "l"(p));
    return a;
}
#define CP16(dst, src) asm volatile("cp.async.cg.shared.global [%0], [%1], 16;" :: "r"(dst), "l"(src))
#define CPC()  asm volatile("cp.async.commit_group;" ::: "memory")
#define CPW0() asm volatile("cp.async.wait_group 0;" ::: "memory")
#define CPW1() asm volatile("cp.async.wait_group 1;" ::: "memory")

__device__ __forceinline__ void ldsm4(u32 &r0, u32 &r1, u32 &r2, u32 &r3, u32 a) {
    asm volatile("ldmatrix.sync.aligned.m8n8.x4.shared.b16 {%0,%1,%2,%3}, [%4];"
        : "=r"(r0), "=r"(r1), "=r"(r2), "=r"(r3) : "r"(a));
}
__device__ __forceinline__ void ldsm4t(u32 &r0, u32 &r1, u32 &r2, u32 &r3, u32 a) {
    asm volatile("ldmatrix.sync.aligned.m8n8.x4.trans.shared.b16 {%0,%1,%2,%3}, [%4];"
        : "=r"(r0), "=r"(r1), "=r"(r2), "=r"(r3) : "r"(a));
}
__device__ __forceinline__ void mmabf(float* d, const u32* a, const u32* b) {
    asm volatile("mma.sync.aligned.m16n8k16.row.col.f32.bf16.bf16.f32 "
        "{%0,%1,%2,%3},{%4,%5,%6,%7},{%8,%9},{%0,%1,%2,%3};"
        : "+f"(d[0]), "+f"(d[1]), "+f"(d[2]), "+f"(d[3])
        : "r"(a[0]), "r"(a[1]), "r"(a[2]), "r"(a[3]), "r"(b[0]), "r"(b[1]));
}
// pack f0(lo half),f1(hi half) to bf16x2 hi; residual pack in lo
__device__ __forceinline__ u32 split2(float f0, float f1, u32 &lo) {
    u32 h; asm("cvt.rn.bf16x2.f32 %0, %1, %2;" : "=r"(h) : "f"(f1), "f"(f0));
    float h0 = __uint_as_float(h << 16);
    float h1 = __uint_as_float(h & 0xffff0000u);
    asm("cvt.rn.bf16x2.f32 %0, %1, %2;" : "=r"(lo) : "f"(f1 - h1), "f"(f0 - h0));
    return h;
}

// ---------------- scratch ----------------
__device__ bf16 g_xh[(size_t)NTOK * DIMM],     g_xl[(size_t)NTOK * DIMM];
__device__ bf16 g_wqh[(size_t)QKV_OUT * DIMM], g_wql[(size_t)QKV_OUT * DIMM];
__device__ bf16 g_woh[(size_t)DIMM * DIMM],    g_wol[(size_t)DIMM * DIMM];
__device__ bf16 g_qh[(size_t)NTOK * NH * HD],  g_ql[(size_t)NTOK * NH * HD];
__device__ bf16 g_kh[(size_t)NTOK * NKV * HD], g_kl[(size_t)NTOK * NKV * HD];
__device__ bf16 g_vh[(size_t)NTOK * NKV * HD], g_vl[(size_t)NTOK * NKV * HD];
__device__ bf16 g_ah[(size_t)NTOK * DIMM],     g_al[(size_t)NTOK * DIMM];

// ---------------- elementwise split fp32 -> bf16 hi/lo ----------------
__global__ __launch_bounds__(256) void split_bf(
    const float4* __restrict__ in, uint2* __restrict__ hi, uint2* __restrict__ lo, int n4)
{
    int i = blockIdx.x * 256 + threadIdx.x;
    if (i >= n4) return;
    float4 v = in[i];
    u32 l0, l1;
    u32 h0 = split2(v.x, v.y, l0);
    u32 h1 = split2(v.z, v.w, l1);
    hi[i] = make_uint2(h0, h1);
    lo[i] = make_uint2(l0, l1);
}

// ---------------- bf16x3 GEMM: C = A[M,K] * B[N,K]^T ----------------
// CTA 128x128, 8 warps (64x32), k32 stages, 3-stage cp.async, 1 sync/stage.
// MODE 0: plain fp32 epilogue to C.
// MODE 1: fused QKV epilogue — n-tile == head; RMSNorm+RoPE+split for Q/K,
//         split-only for V; writes bf16 hi/lo planes directly.
#define GEMM_SMEM (3 * 32768)
template<int MODE>
__global__ __launch_bounds__(256, 2) void gemm_bf3(
    const bf16* __restrict__ Ah, const bf16* __restrict__ Al,
    const bf16* __restrict__ Bh, const bf16* __restrict__ Bl,
    float* __restrict__ C, int M, int N, int K,
    const float* __restrict__ freqs,
    const float* __restrict__ qw, const float* __restrict__ kw)
{
    extern __shared__ char gsm[];
    const u32 sb = smem_u32(gsm);
    const int tid = threadIdx.x, L = tid & 31, w = tid >> 5;
    const int m0 = blockIdx.y * 128, n0 = blockIdx.x * 128;
    const int mw = w & 1, nq = w >> 1;

    float acc[4][4][4];
    #pragma unroll
    for (int a = 0; a < 4; a++)
        #pragma unroll
        for (int b = 0; b < 4; b++)
            #pragma unroll
            for (int c = 0; c < 4; c++) acc[a][b][c] = 0.f;

    const int NS = K >> 5;

    #define GEMM_STAGE_CP(s) do { \
        int k0 = (s) * 32; \
        u32 bufb = sb + ((s) % 3) * 32768; \
        _Pragma("unroll") \
        for (int rr = 0; rr < 4; rr++) { \
            int id = tid + rr * 256; \
            int row = id >> 3, c = id & 7, pl = c >> 2, kc = c & 3; \
            const bf16* srcA = (pl ? Al : Ah) + (size_t)(m0 + row) * K + k0 + kc * 8; \
            CP16(bufb + row * 128 + (((u32)(c ^ (row & 7))) << 4), srcA); \
            const bf16* srcB = (pl ? Bl : Bh) + (size_t)(n0 + row) * K + k0 + kc * 8; \
            CP16(bufb + 16384 + row * 128 + (((u32)(c ^ (row & 7))) << 4), srcB); \
        } \
    } while (0)

    GEMM_STAGE_CP(0); CPC();
    GEMM_STAGE_CP(1); CPC();

    for (int s = 0; s < NS; s++) {
        CPW1();
        __syncthreads();
        if (s + 2 < NS) { GEMM_STAGE_CP(s + 2); CPC(); }
        u32 ab = sb + (s % 3) * 32768;
        u32 bb = ab + 16384;
        #pragma unroll
        for (int ks = 0; ks < 2; ks++) {
            u32 ah[4][4], al[4][4], bh[4][2], bl[4][2];
            #pragma unroll
            for (int mt = 0; mt < 4; mt++) {
                int row = mw * 64 + mt * 16 + (L & 7) + ((L >> 3) & 1) * 8;
                int ch = ks * 2 + (L >> 4);
                u32 base = ab + row * 128;
                ldsm4(ah[mt][0], ah[mt][1], ah[mt][2], ah[mt][3],
                      base + ((u32)(ch ^ (row & 7)) << 4));
                ldsm4(al[mt][0], al[mt][1], al[mt][2], al[mt][3],
                      base + ((u32)((ch + 4) ^ (row & 7)) << 4));
            }
            #pragma unroll
            for (int p = 0; p < 2; p++) {
                int row = nq * 32 + p * 16 + (L & 7) + (L >> 4) * 8;
                int ch = ks * 2 + ((L >> 3) & 1);
                u32 base = bb + row * 128;
                u32 r0, r1, r2, r3;
                ldsm4(r0, r1, r2, r3, base + ((u32)(ch ^ (row & 7)) << 4));
                bh[2*p][0] = r0; bh[2*p][1] = r1; bh[2*p+1][0] = r2; bh[2*p+1][1] = r3;
                ldsm4(r0, r1, r2, r3, base + ((u32)((ch + 4) ^ (row & 7)) << 4));
                bl[2*p][0] = r0; bl[2*p][1] = r1; bl[2*p+1][0] = r2; bl[2*p+1][1] = r3;
            }
            #pragma unroll
            for (int mt = 0; mt < 4; mt++)
                #pragma unroll
                for (int nt = 0; nt < 4; nt++) {
                    mmabf(acc[mt][nt], ah[mt], bh[nt]);
                    mmabf(acc[mt][nt], ah[mt], bl[nt]);
                    mmabf(acc[mt][nt], al[mt], bh[nt]);
                }
        }
        __syncthreads();
    }

    if (MODE == 0) {
        #pragma unroll
        for (int mt = 0; mt < 4; mt++) {
            int r0 = m0 + mw * 64 + mt * 16 + (L >> 2);
            #pragma unroll
            for (int nt = 0; nt < 4; nt++) {
                int c0 = n0 + nq * 32 + nt * 8 + (L & 3) * 2;
                *(float2*)(C + (size_t)r0 * N + c0)       = make_float2(acc[mt][nt][0], acc[mt][nt][1]);
                *(float2*)(C + (size_t)(r0 + 8) * N + c0) = make_float2(acc[mt][nt][2], acc[mt][nt][3]);
            }
        }
    } else {
        // -------- fused QKV epilogue --------
        const int nb = blockIdx.x;   // 0..15 Q heads, 16..23 K heads, 24..31 V heads
        if (nb >= 24) {
            // V: straight bf16 split; layout [t][kv*128]
            const int h = nb - 24;
            #pragma unroll
            for (int mt = 0; mt < 4; mt++) {
                int rowA = mw * 64 + mt * 16 + (L >> 2);
                int tA = m0 + rowA;
                #pragma unroll
                for (int nt = 0; nt < 4; nt++) {
                    int d = nq * 32 + nt * 8 + (L & 3) * 2;
                    size_t iA = ((size_t)tA * NKV + h) * HD + d;
                    size_t iB = ((size_t)(tA + 8) * NKV + h) * HD + d;
                    u32 lo_;
                    u32 hi_ = split2(acc[mt][nt][0], acc[mt][nt][1], lo_);
                    *(u32*)&g_vh[iA] = hi_; *(u32*)&g_vl[iA] = lo_;
                    hi_ = split2(acc[mt][nt][2], acc[mt][nt][3], lo_);
                    *(u32*)&g_vh[iB] = hi_; *(u32*)&g_vl[iB] = lo_;
                }
            }
        } else {
            __shared__ float ssred[128][5];
            __shared__ float ssfin[128];
            // per-row sum of squares
            float pA[4], pB[4];
            #pragma unroll
            for (int mt = 0; mt < 4; mt++) {
                float sA = 0.f, sB = 0.f;
                #pragma unroll
                for (int nt = 0; nt < 4; nt++) {
                    sA += acc[mt][nt][0] * acc[mt][nt][0] + acc[mt][nt][1] * acc[mt][nt][1];
                    sB += acc[mt][nt][2] * acc[mt][nt][2] + acc[mt][nt][3] * acc[mt][nt][3];
                }
                pA[mt] = sA; pB[mt] = sB;
            }
            #pragma unroll
            for (int o = 1; o < 4; o <<= 1) {
                #pragma unroll
                for (int mt = 0; mt < 4; mt++) {
                    pA[mt] += __shfl_xor_sync(0xffffffffu, pA[mt], o);
                    pB[mt] += __shfl_xor_sync(0xffffffffu, pB[mt], o);
                }
            }
            if ((L & 3) == 0) {
                #pragma unroll
                for (int mt = 0; mt < 4; mt++) {
                    int rowA = mw * 64 + mt * 16 + (L >> 2);
                    ssred[rowA][nq] = pA[mt];
                    ssred[rowA + 8][nq] = pB[mt];
                }
            }
            __syncthreads();
            if (tid < 128)
                ssfin[tid] = ssred[tid][0] + ssred[tid][1] + ssred[tid][2] + ssred[tid][3];
            __syncthreads();

            const bool isq = nb < 16;
            const int h = isq ? nb : nb - 16;
            const float* wv = isq ? qw : kw;
            #pragma unroll
            for (int mt = 0; mt < 4; mt++) {
                int rowA = mw * 64 + mt * 16 + (L >> 2);
                int tA = m0 + rowA, tB = tA + 8;
                float nfA = rsqrtf(ssfin[rowA]     * (1.0f / HD) + 1e-5f);
                float nfB = rsqrtf(ssfin[rowA + 8] * (1.0f / HD) + 1e-5f);
                int sA = tA & (S_LEN - 1), sB = tB & (S_LEN - 1);
                #pragma unroll
                for (int nt = 0; nt < 4; nt++) {
                    int d = nq * 32 + nt * 8 + (L & 3) * 2;
                    float2 wp = *(const float2*)(wv + d);
                    int f = d >> 1;
                    float4 fcA = *(const float4*)(freqs + ((size_t)sA * 64 + f) * 4);
                    float4 fcB = *(const float4*)(freqs + ((size_t)sB * 64 + f) * 4);
                    // token A
                    {
                        float x0 = acc[mt][nt][0] * nfA * wp.x;
                        float x1 = acc[mt][nt][1] * nfA * wp.y;
                        float o0 = fcA.x * x0 + fcA.y * x1;
                        float o1 = fcA.z * x0 + fcA.w * x1;
                        u32 lo_; u32 hi_ = split2(o0, o1, lo_);
                        if (isq) {
                            size_t i = ((size_t)tA * NH + h) * HD + d;
                            *(u32*)&g_qh[i] = hi_; *(u32*)&g_ql[i] = lo_;
                        } else {
                            size_t i = ((size_t)tA * NKV + h) * HD + d;
                            *(u32*)&g_kh[i] = hi_; *(u32*)&g_kl[i] = lo_;
                        }
                    }
                    // token B
                    {
                        float x0 = acc[mt][nt][2] * nfB * wp.x;
                        float x1 = acc[mt][nt][3] * nfB * wp.y;
                        float o0 = fcB.x * x0 + fcB.y * x1;
                        float o1 = fcB.z * x0 + fcB.w * x1;
                        u32 lo_; u32 hi_ = split2(o0, o1, lo_);
                        if (isq) {
                            size_t i = ((size_t)tB * NH + h) * HD + d;
                            *(u32*)&g_qh[i] = hi_; *(u32*)&g_ql[i] = lo_;
                        } else {
                            size_t i = ((size_t)tB * NKV + h) * HD + d;
                            *(u32*)&g_kh[i] = hi_; *(u32*)&g_kl[i] = lo_;
                        }
                    }
                }
            }
        }
    }
}

// ---------------- tensor-core flash attention (bf16x3) ----------------
// grid (S/128, NH, B), 256 threads. smem: Q 64KB + 2 x (K 32KB + V 32KB) = 192KB.
#define FL_SMEM (65536 + 2 * 65536)
__global__ __launch_bounds__(256, 1) void flash_bf(const float* __restrict__ mask)
{
    extern __shared__ char fsm[];
    const u32 sb = smem_u32(fsm);
    const int tid = threadIdx.x, L = tid & 31, w = tid >> 5;
    const int h = blockIdx.y, b = blockIdx.z;
    const int hkv = h >> 1;
    const int q0 = blockIdx.x * 128;
    const int tok0 = b * S_LEN;
    const float scale = 0.088388347762f;

    #pragma unroll
    for (int i = 0; i < 16; i++) {
        int id = tid + i * 256;
        int row = id >> 5, c = id & 31, pl = c >> 4, cc = c & 15;
        const bf16* src = (pl ? g_ql : g_qh)
            + ((size_t)(tok0 + q0 + row) * NH + h) * HD + cc * 8;
        CP16(sb + row * 512 + ((u32)(c ^ (row & 7)) << 4), src);
    }
    CPC();

    #define FL_KV_CP(tt) do { \
        u32 bufb = sb + 65536 + ((tt) & 1) * 65536; \
        int kt_ = (tt) * 64; \
        _Pragma("unroll") \
        for (int i = 0; i < 16; i++) { \
            int id = tid + i * 256; \
            int tensor = id >> 11; \
            int rem = id & 2047; \
            int row = rem >> 5, c = rem & 31, pl = c >> 4, cc = c & 15; \
            const bf16* src; \
            if (tensor == 0) src = (pl ? g_kl : g_kh) \
                + ((size_t)(tok0 + kt_ + row) * NKV + hkv) * HD + cc * 8; \
            else             src = (pl ? g_vl : g_vh) \
                + ((size_t)(tok0 + kt_ + row) * NKV + hkv) * HD + cc * 8; \
            CP16(bufb + tensor * 32768 + row * 512 + ((u32)(c ^ (row & 7)) << 4), src); \
        } \
    } while (0)

    FL_KV_CP(0); CPC();

    float m0r = -1e30f, m1r = -1e30f, l0r = 0.f, l1r = 0.f;
    float acc[16][4];
    #pragma unroll
    for (int i = 0; i < 16; i++)
        #pragma unroll
        for (int j = 0; j < 4; j++) acc[i][j] = 0.f;

    const int g = L >> 2;
    const float* mp0 = mask + (size_t)b * S_LEN * S_LEN
                       + (size_t)(q0 + w * 16 + g) * S_LEN + (L & 3) * 2;

    for (int t = 0; t < 32; t++) {
        if (t + 1 < 32) { FL_KV_CP(t + 1); CPC(); CPW1(); }
        else CPW0();
        __syncthreads();
        u32 kb = sb + 65536 + (t & 1) * 65536;
        u32 vb = kb + 32768;
        const int kt = t * 64;

        float s[8][4];
        #pragma unroll
        for (int f = 0; f < 8; f++)
            #pragma unroll
            for (int j = 0; j < 4; j++) s[f][j] = 0.f;

        #pragma unroll
        for (int kd = 0; kd < 8; kd++) {
            u32 qh[4], ql[4];
            {
                int row = w * 16 + (L & 7) + ((L >> 3) & 1) * 8;
                int ch = kd * 2 + (L >> 4);
                u32 base = sb + row * 512;
                ldsm4(qh[0], qh[1], qh[2], qh[3], base + ((u32)(ch ^ (row & 7)) << 4));
                ldsm4(ql[0], ql[1], ql[2], ql[3], base + ((u32)((ch + 16) ^ (row & 7)) << 4));
            }
            u32 kh[8][2], kl[8][2];
            #pragma unroll
            for (int p = 0; p < 4; p++) {
                int row = p * 16 + (L & 7) + (L >> 4) * 8;
                int ch = kd * 2 + ((L >> 3) & 1);
                u32 base = kb + row * 512;
                u32 r0, r1, r2, r3;
                ldsm4(r0, r1, r2, r3, base + ((u32)(ch ^ (row & 7)) << 4));
                kh[2*p][0] = r0; kh[2*p][1] = r1; kh[2*p+1][0] = r2; kh[2*p+1][1] = r3;
                ldsm4(r0, r1, r2, r3, base + ((u32)((ch + 16) ^ (row & 7)) << 4));
                kl[2*p][0] = r0; kl[2*p][1] = r1; kl[2*p+1][0] = r2; kl[2*p+1][1] = r3;
            }
            #pragma unroll
            for (int f = 0; f < 8; f++) {
                mmabf(s[f], qh, kh[f]);
                mmabf(s[f], qh, kl[f]);
                mmabf(s[f], ql, kh[f]);
            }
        }

        float mx0 = -1e30f, mx1 = -1e30f;
        #pragma unroll
        for (int f = 0; f < 8; f++) {
            float2 mv0 = *(const float2*)(mp0 + kt + f * 8);
            float2 mv1 = *(const float2*)(mp0 + 8 * S_LEN + kt + f * 8);
            s[f][0] = s[f][0] * scale + mv0.x;
            s[f][1] = s[f][1] * scale + mv0.y;
            s[f][2] = s[f][2] * scale + mv1.x;
            s[f][3] = s[f][3] * scale + mv1.y;
            mx0 = fmaxf(mx0, fmaxf(s[f][0], s[f][1]));
            mx1 = fmaxf(mx1, fmaxf(s[f][2], s[f][3]));
        }
        mx0 = fmaxf(mx0, __shfl_xor_sync(0xffffffffu, mx0, 1));
        mx0 = fmaxf(mx0, __shfl_xor_sync(0xffffffffu, mx0, 2));
        mx1 = fmaxf(mx1, __shfl_xor_sync(0xffffffffu, mx1, 1));
        mx1 = fmaxf(mx1, __shfl_xor_sync(0xffffffffu, mx1, 2));
        float mn0 = fmaxf(m0r, mx0), mn1 = fmaxf(m1r, mx1);
        float a0 = __expf(m0r - mn0), a1 = __expf(m1r - mn1);
        m0r = mn0; m1r = mn1;
        float sum0 = 0.f, sum1 = 0.f;
        #pragma unroll
        for (int f = 0; f < 8; f++) {
            s[f][0] = __expf(s[f][0] - mn0); sum0 += s[f][0];
            s[f][1] = __expf(s[f][1] - mn0); sum0 += s[f][1];
            s[f][2] = __expf(s[f][2] - mn1); sum1 += s[f][2];
            s[f][3] = __expf(s[f][3] - mn1); sum1 += s[f][3];
        }
        sum0 += __shfl_xor_sync(0xffffffffu, sum0, 1);
        sum0 += __shfl_xor_sync(0xffffffffu, sum0, 2);
        sum1 += __shfl_xor_sync(0xffffffffu, sum1, 1);
        sum1 += __shfl_xor_sync(0xffffffffu, sum1, 2);
        l0r = l0r * a0 + sum0;
        l1r = l1r * a1 + sum1;

        u32 ph[4][4], pl[4][4];
        #pragma unroll
        for (int kg = 0; kg < 4; kg++) {
            ph[kg][0] = split2(s[2*kg][0],   s[2*kg][1],   pl[kg][0]);
            ph[kg][1] = split2(s[2*kg][2],   s[2*kg][3],   pl[kg][1]);
            ph[kg][2] = split2(s[2*kg+1][0], s[2*kg+1][1], pl[kg][2]);
            ph[kg][3] = split2(s[2*kg+1][2], s[2*kg+1][3], pl[kg][3]);
        }

        #pragma unroll
        for (int df = 0; df < 16; df++) {
            acc[df][0] *= a0; acc[df][1] *= a0;
            acc[df][2] *= a1; acc[df][3] *= a1;
        }

        #pragma unroll
        for (int kg = 0; kg < 4; kg++) {
            #pragma unroll
            for (int dp = 0; dp < 8; dp++) {
                int row = kg * 16 + (L & 7) + ((L >> 3) & 1) * 8;
                int ch = dp * 2 + (L >> 4);
                u32 base = vb + row * 512;
                u32 vh0[2], vh1[2], vl0[2], vl1[2];
                {
                    u32 r0, r1, r2, r3;
                    ldsm4t(r0, r1, r2, r3, base + ((u32)(ch ^ (row & 7)) << 4));
                    vh0[0] = r0; vh0[1] = r1; vh1[0] = r2; vh1[1] = r3;
                    ldsm4t(r0, r1, r2, r3, base + ((u32)((ch + 16) ^ (row & 7)) << 4));
                    vl0[0] = r0; vl0[1] = r1; vl1[0] = r2; vl1[1] = r3;
                }
                mmabf(acc[2*dp],   ph[kg], vh0);
                mmabf(acc[2*dp],   ph[kg], vl0);
                mmabf(acc[2*dp],   pl[kg], vh0);
                mmabf(acc[2*dp+1], ph[kg], vh1);
                mmabf(acc[2*dp+1], ph[kg], vl1);
                mmabf(acc[2*dp+1], pl[kg], vh1);
            }
        }
        __syncthreads();
    }

    float inv0 = 1.0f / l0r, inv1 = 1.0f / l1r;
    int qrow = tok0 + q0 + w * 16 + g;
    #pragma unroll
    for (int df = 0; df < 16; df++) {
        int col = h * HD + df * 8 + (L & 3) * 2;
        u32 lo_;
        u32 hi_ = split2(acc[df][0] * inv0, acc[df][1] * inv0, lo_);
        *(u32*)&g_ah[(size_t)qrow * DIMM + col] = hi_;
        *(u32*)&g_al[(size_t)qrow * DIMM + col] = lo_;
        hi_ = split2(acc[df][2] * inv1, acc[df][3] * inv1, lo_);
        *(u32*)&g_ah[(size_t)(qrow + 8) * DIMM + col] = hi_;
        *(u32*)&g_al[(size_t)(qrow + 8) * DIMM + col] = lo_;
    }
}

// ---------------- launch ----------------
extern "C" void kernel_launch(void* const* d_in, const int* in_sizes, int n_in,
                              void* d_out, int out_size)
{
    const float* x     = (const float*)d_in[0];
    const float* mask  = (const float*)d_in[1];
    const float* freqs = (const float*)d_in[2];
    const float* w_qkv = (const float*)d_in[3];
    const float* w_out = (const float*)d_in[4];
    const float* q_w   = (const float*)d_in[5];
    const float* k_w   = (const float*)d_in[6];
    float* out = (float*)d_out;

    bf16 *xh, *xl, *wqh, *wql, *woh, *wol, *ah, *al;
    cudaGetSymbolAddress((void**)&xh,  g_xh);  cudaGetSymbolAddress((void**)&xl,  g_xl);
    cudaGetSymbolAddress((void**)&wqh, g_wqh); cudaGetSymbolAddress((void**)&wql, g_wql);
    cudaGetSymbolAddress((void**)&woh, g_woh); cudaGetSymbolAddress((void**)&wol, g_wol);
    cudaGetSymbolAddress((void**)&ah,  g_ah);  cudaGetSymbolAddress((void**)&al,  g_al);

    cudaFuncSetAttribute(gemm_bf3<0>, cudaFuncAttributeMaxDynamicSharedMemorySize, GEMM_SMEM);
    cudaFuncSetAttribute(gemm_bf3<1>, cudaFuncAttributeMaxDynamicSharedMemorySize, GEMM_SMEM);
    cudaFuncSetAttribute(flash_bf,    cudaFuncAttributeMaxDynamicSharedMemorySize, FL_SMEM);

    const int N4_X  = NTOK * DIMM / 4;
    const int N4_WQ = QKV_OUT * DIMM / 4;
    const int N4_WO = DIMM * DIMM / 4;

    split_bf<<<(N4_X  + 255)/256, 256>>>((const float4*)x,     (uint2*)xh,  (uint2*)xl,  N4_X);
    split_bf<<<(N4_WQ + 255)/256, 256>>>((const float4*)w_qkv, (uint2*)wqh, (uint2*)wql, N4_WQ);
    split_bf<<<(N4_WO + 255)/256, 256>>>((const float4*)w_out, (uint2*)woh, (uint2*)wol, N4_WO);

    // QKV projection with fused RMSNorm+RoPE+split epilogue
    gemm_bf3<1><<<dim3(QKV_OUT/128, NTOK/128), 256, GEMM_SMEM>>>(
        xh, xl, wqh, wql, nullptr, NTOK, QKV_OUT, DIMM, freqs, q_w, k_w);

    flash_bf<<<dim3(S_LEN/128, NH, 2), 256, FL_SMEM>>>(mask);

    // out projection
    gemm_bf3<0><<<dim3(DIMM/128, NTOK/128), 256, GEMM_SMEM>>>(
        ah, al, woh, wol, out, NTOK, DIMM, DIMM, nullptr, nullptr, nullptr);
}